// round 5
// baseline (speedup 1.0000x reference)
#include <cuda_runtime.h>
#include <math_constants.h>

// Problem constants (match reference setup_inputs)
#define NROWS 131072
#define D     128
#define NC    512

// Tiling
#define R_TILE   64          // rows per CTA
#define CHUNK    64          // codebook rows per smem chunk
#define THREADS  512

#define XS_STRIDE 130        // 128 + 2 pad (even, conflict-free for LDS.64)
#define CS_STRIDE 130
#define L_STRIDE  516        // 512 + 4 pad (multiple of 4 -> float4-aligned rows)

#define SMEM_FLOATS (2 * R_TILE * XS_STRIDE + R_TILE * L_STRIDE)  // 49664
#define SMEM_BYTES  (SMEM_FLOATS * 4)                              // 198656

#define ARG_MARGIN 1e-5f

__device__ __forceinline__ void fma2(unsigned long long& acc,
                                     unsigned long long a,
                                     unsigned long long b) {
    asm("fma.rn.f32x2 %0, %1, %2, %0;" : "+l"(acc) : "l"(a), "l"(b));
}

__device__ __forceinline__ unsigned long long dup2(float v) {
    unsigned long long r;
    asm("mov.b64 %0, {%1, %1};" : "=l"(r) : "f"(v));
    return r;
}

__device__ __forceinline__ float2 unpack2(unsigned long long v) {
    float2 r;
    asm("mov.b64 {%0, %1}, %2;" : "=f"(r.x), "=f"(r.y) : "l"(v));
    return r;
}

__global__ void __launch_bounds__(THREADS)
gumbel_vq_kernel(const float* __restrict__ x,
                 const float* __restrict__ mask,
                 const float* __restrict__ codebook,
                 const float* __restrict__ noise,
                 float* __restrict__ out_q,    // (n, 128)
                 float* __restrict__ out_e,    // (n, 512)
                 float* __restrict__ out_i)    // (n,) indices as float
{
    extern __shared__ float sm[];
    float* xs = sm;                                  // [R_TILE][XS_STRIDE]
    float* cs = sm + R_TILE * XS_STRIDE;             // [CHUNK][CS_STRIDE]
    float* L  = sm + 2 * R_TILE * XS_STRIDE;         // [R_TILE][L_STRIDE]

    const int t    = threadIdx.x;
    const int row0 = blockIdx.x * R_TILE;

    // ---------------- Load x tile (with mask nudge) ----------------
    for (int f = t; f < R_TILE * D / 4; f += THREADS) {
        int r  = f >> 5;               // 32 float4 per row
        int c4 = (f & 31) << 2;
        float4 v = *reinterpret_cast<const float4*>(x + (size_t)(row0 + r) * D + c4);
        float nud = (1.0f - mask[row0 + r]) * 1e-6f;
        v.x += nud; v.y += nud; v.z += nud; v.w += nud;
        float* dst = xs + r * XS_STRIDE + c4;
        *reinterpret_cast<float2*>(dst)     = make_float2(v.x, v.y);
        *reinterpret_cast<float2*>(dst + 2) = make_float2(v.z, v.w);
    }
    __syncthreads();

    // ---------------- Row normalize (8 threads / row) ----------------
    // fp64 sumsq -> fp32 norm -> elementwise IEEE fp32 division (matches ref).
    {
        int r = t >> 3, q = t & 7;
        float* xr = xs + r * XS_STRIDE + q * 16;
        double s = 0.0;
        #pragma unroll
        for (int k = 0; k < 16; k++) { double v = (double)xr[k]; s += v * v; }
        s += __shfl_xor_sync(0xFFFFFFFFu, s, 1);
        s += __shfl_xor_sync(0xFFFFFFFFu, s, 2);
        s += __shfl_xor_sync(0xFFFFFFFFu, s, 4);
        float nf = (float)sqrt(s);
        nf = fmaxf(nf, 1e-6f);
        #pragma unroll
        for (int k = 0; k < 16; k++) xr[k] = xr[k] / nf;   // IEEE fp32 div
    }
    __syncthreads();

    const int ty = t >> 4;   // 0..31 (row groups of 2)
    const int tx = t & 15;   // 0..15

    // ---------------- GEMM1: ab = xn @ C^T, write to L ----------------
    // thread tile: 2 rows x 4 codes (codes tx + 16j)
    for (int cb = 0; cb < NC; cb += CHUNK) {
        for (int f = t; f < CHUNK * D / 4; f += THREADS) {
            int r  = f >> 5;
            int c4 = (f & 31) << 2;
            float4 v = *reinterpret_cast<const float4*>(codebook + (size_t)(cb + r) * D + c4);
            float* dst = cs + r * CS_STRIDE + c4;
            *reinterpret_cast<float2*>(dst)     = make_float2(v.x, v.y);
            *reinterpret_cast<float2*>(dst + 2) = make_float2(v.z, v.w);
        }
        __syncthreads();

        unsigned long long acc[2][4];
        #pragma unroll
        for (int i = 0; i < 2; i++)
            #pragma unroll
            for (int j = 0; j < 4; j++) acc[i][j] = 0ull;

        const float* xb  = xs + (2 * ty) * XS_STRIDE;
        const float* cbp = cs + tx * CS_STRIDE;

        #pragma unroll 8
        for (int k2 = 0; k2 < 64; k2++) {
            unsigned long long a2[2], b2[4];
            #pragma unroll
            for (int i = 0; i < 2; i++)
                a2[i] = *reinterpret_cast<const unsigned long long*>(xb + i * XS_STRIDE + 2 * k2);
            #pragma unroll
            for (int j = 0; j < 4; j++)
                b2[j] = *reinterpret_cast<const unsigned long long*>(cbp + 16 * j * CS_STRIDE + 2 * k2);
            #pragma unroll
            for (int i = 0; i < 2; i++)
                #pragma unroll
                for (int j = 0; j < 4; j++)
                    fma2(acc[i][j], a2[i], b2[j]);
        }

        #pragma unroll
        for (int i = 0; i < 2; i++) {
            #pragma unroll
            for (int j = 0; j < 4; j++) {
                float2 p = unpack2(acc[i][j]);
                L[(2 * ty + i) * L_STRIDE + cb + tx + 16 * j] = p.x + p.y;
            }
        }
        __syncthreads();
    }

    // ---------------- Argmin + Softmax, register-resident (8 threads / row) ----
    {
        int r = t >> 3, g = t & 7;
        const int gr = row0 + r;
        float* Lr = L + r * L_STRIDE;
        const float* nzr = noise + (size_t)gr * NC;

        // interleaved float4 ownership: thread g owns float4 blocks (kk*8+g), kk=0..15
        float v[64];
        float vmax = -CUDART_INF_F;
        float m1 = -CUDART_INF_F, m2 = -CUDART_INF_F;
        int i1 = 1 << 30;

        #pragma unroll
        for (int kk = 0; kk < 16; kk++) {
            int c4 = (kk * 8 + g) * 4;
            float4 ab4 = *reinterpret_cast<const float4*>(Lr + c4);
            float4 nv  = *reinterpret_cast<const float4*>(nzr + c4);
            float ab[4] = {ab4.x, ab4.y, ab4.z, ab4.w};
            float nn[4] = {nv.x,  nv.y,  nv.z,  nv.w};
            #pragma unroll
            for (int jj = 0; jj < 4; jj++) {
                float a = ab[jj];
                float lv = 2.0f * a + nn[jj];
                v[kk * 4 + jj] = lv;
                vmax = fmaxf(vmax, lv);
                if (a > m1) { m2 = m1; m1 = a; i1 = c4 + jj; }
                else        { m2 = fmaxf(m2, a); }
            }
        }

        // reduce across the 8 lanes of this row
        #pragma unroll
        for (int dlt = 1; dlt <= 4; dlt <<= 1) {
            vmax = fmaxf(vmax, __shfl_xor_sync(0xFFFFFFFFu, vmax, dlt));
            float om1 = __shfl_xor_sync(0xFFFFFFFFu, m1, dlt);
            float om2 = __shfl_xor_sync(0xFFFFFFFFu, m2, dlt);
            int   oi1 = __shfl_xor_sync(0xFFFFFFFFu, i1, dlt);
            if (om1 > m1)       { m2 = fmaxf(m1, om2); m1 = om1; i1 = oi1; }
            else if (om1 == m1) { m2 = m1; i1 = min(i1, oi1); }
            else                { m2 = fmaxf(m2, om1); }
        }

        int final_idx = i1;
        if (!(m1 - m2 > ARG_MARGIN)) {
            // tier 2: replicate reference arithmetic on near-max candidates:
            // serial ascending-k fp32 FMA dot, then d = (1 - 2*ab) + 1,
            // argmin with first-index tie-break. L still holds ab here.
            unsigned sub = 0xFFu << ((t & 31) & ~7);   // this row's 8 lanes
            const float* xr = xs + r * XS_STRIDE;
            float bd = CUDART_INF_F;
            int bi = 1 << 30;
            float thresh = m1 - ARG_MARGIN;
            for (int kk = 0; kk < 16; kk++) {
                int c4 = (kk * 8 + g) * 4;
                #pragma unroll
                for (int jj = 0; jj < 4; jj++) {
                    if (Lr[c4 + jj] >= thresh) {
                        const float* cj = codebook + (size_t)(c4 + jj) * D;
                        float acc = 0.0f;
                        #pragma unroll 8
                        for (int kd = 0; kd < 128; kd++)
                            acc = fmaf(xr[kd], cj[kd], acc);   // serial ascending k
                        float df = (1.0f - 2.0f * acc) + 1.0f;
                        int ci = c4 + jj;
                        if (df < bd || (df == bd && ci < bi)) { bd = df; bi = ci; }
                    }
                }
            }
            #pragma unroll
            for (int dlt = 1; dlt <= 4; dlt <<= 1) {
                float od = __shfl_xor_sync(sub, bd, dlt);
                int   oi = __shfl_xor_sync(sub, bi, dlt);
                if (od < bd || (od == bd && oi < bi)) { bd = od; bi = oi; }
            }
            final_idx = bi;
        }
        if (g == 0) out_i[gr] = (float)final_idx;

        // exp + sum (registers)
        float s = 0.f;
        #pragma unroll
        for (int k = 0; k < 64; k++) {
            float e = __expf(v[k] - vmax);
            v[k] = e;
            s += e;
        }
        s += __shfl_xor_sync(0xFFFFFFFFu, s, 1);
        s += __shfl_xor_sync(0xFFFFFFFFu, s, 2);
        s += __shfl_xor_sync(0xFFFFFFFFu, s, 4);
        float inv = 1.0f / s;

        // normalize, write encodings to smem (for GEMM2) and global
        float* ez = out_e + (size_t)gr * NC;
        #pragma unroll
        for (int kk = 0; kk < 16; kk++) {
            int c4 = (kk * 8 + g) * 4;
            float4 ev;
            ev.x = v[kk * 4 + 0] * inv;
            ev.y = v[kk * 4 + 1] * inv;
            ev.z = v[kk * 4 + 2] * inv;
            ev.w = v[kk * 4 + 3] * inv;
            *reinterpret_cast<float4*>(Lr + c4) = ev;
            *reinterpret_cast<float4*>(ez + c4) = ev;
        }
    }

    // ---------------- GEMM2: quantized = enc @ C ----------------
    // thread tile: 2 rows x 4 f32x2 d-col pairs (cols 2tx + 32j)
    unsigned long long qa[2][4];
    #pragma unroll
    for (int i = 0; i < 2; i++)
        #pragma unroll
        for (int j = 0; j < 4; j++) qa[i][j] = 0ull;

    for (int cb = 0; cb < NC; cb += CHUNK) {
        __syncthreads();   // softmax L writes done / prev chunk consumers done
        for (int f = t; f < CHUNK * D / 4; f += THREADS) {
            int r  = f >> 5;
            int c4 = (f & 31) << 2;
            float4 v = *reinterpret_cast<const float4*>(codebook + (size_t)(cb + r) * D + c4);
            float* dst = cs + r * CS_STRIDE + c4;
            *reinterpret_cast<float2*>(dst)     = make_float2(v.x, v.y);
            *reinterpret_cast<float2*>(dst + 2) = make_float2(v.z, v.w);
        }
        __syncthreads();

        const float* Lb = L + (2 * ty) * L_STRIDE + cb;
        #pragma unroll 8
        for (int cc = 0; cc < CHUNK; cc++) {
            unsigned long long e2[2], b2[4];
            #pragma unroll
            for (int i = 0; i < 2; i++)
                e2[i] = dup2(Lb[i * L_STRIDE + cc]);
            #pragma unroll
            for (int j = 0; j < 4; j++)
                b2[j] = *reinterpret_cast<const unsigned long long*>(cs + cc * CS_STRIDE + 2 * tx + 32 * j);
            #pragma unroll
            for (int i = 0; i < 2; i++)
                #pragma unroll
                for (int j = 0; j < 4; j++)
                    fma2(qa[i][j], e2[i], b2[j]);
        }
    }

    #pragma unroll
    for (int i = 0; i < 2; i++) {
        #pragma unroll
        for (int j = 0; j < 4; j++) {
            float2 p = unpack2(qa[i][j]);
            *reinterpret_cast<float2*>(out_q + (size_t)(row0 + 2 * ty + i) * D + 2 * tx + 32 * j) = p;
        }
    }
}

extern "C" void kernel_launch(void* const* d_in, const int* in_sizes, int n_in,
                              void* d_out, int out_size) {
    const float* x        = (const float*)d_in[0];   // (131072, 128)
    const float* mask     = (const float*)d_in[1];   // (131072,)
    const float* codebook = (const float*)d_in[2];   // (512, 128)
    const float* noise    = (const float*)d_in[3];   // (131072, 512)

    float* out   = (float*)d_out;
    float* out_q = out;                                   // (n, 128)
    float* out_e = out + (size_t)NROWS * D;               // (n, 512)
    float* out_i = out_e + (size_t)NROWS * NC;            // (n,)

    cudaFuncSetAttribute(gumbel_vq_kernel,
                         cudaFuncAttributeMaxDynamicSharedMemorySize, SMEM_BYTES);

    dim3 grid(NROWS / R_TILE);
    gumbel_vq_kernel<<<grid, THREADS, SMEM_BYTES>>>(x, mask, codebook, noise,
                                                    out_q, out_e, out_i);
}